// round 7
// baseline (speedup 1.0000x reference)
#include <cuda_runtime.h>
#include <cuda_fp16.h>
#include <cstdint>

#define N_NODES 100000
#define N_EDGES 3200000
#define D       64
#define NH      128

// ---------------------------------------------------------------------------
// Scratch (allocation-free rule: __device__ globals)
// ---------------------------------------------------------------------------
__device__ __half g_Ah[(size_t)N_NODES * NH];   // 25.6 MB
__device__ __half g_Bh[(size_t)N_NODES * NH];   // 25.6 MB
__device__ unsigned char g_Wh[256 * 128];       // fused W fp16 hi (swizzled)
__device__ unsigned char g_Wl[256 * 128];       // fused W fp16 lo (swizzled)

// sort scratch
__device__ unsigned int g_cnt[N_NODES];
__device__ unsigned int g_off[N_NODES];
__device__ unsigned int g_cur[N_NODES];
__device__ unsigned int g_bsum[128];
__device__ unsigned int g_bsc[128];
__device__ int g_rowS[N_EDGES];
__device__ int g_colS[N_EDGES];
__device__ int g_permS[N_EDGES];

// ---------------------------------------------------------------------------
// smem layout for node_mma (bytes)
// ---------------------------------------------------------------------------
#define SM_B1   0            // 512 B
#define SM_ZH   512          // 16 KB  zh [128 rows][128 B]
#define SM_WH   16896        // 32 KB  Wh [256 rows][128 B]
#define SM_WL   49664        // 32 KB  Wl
#define SM_TOT  82432

// ---------------------------------------------------------------------------
// Kernel 0: build split fp16 weight tables (swizzled).
// ---------------------------------------------------------------------------
__global__ void build_wt(const float* __restrict__ W1) {
    int idx = blockIdx.x * 256 + threadIdx.x;   // 0..16383
    int n = idx >> 6;
    int k = idx & 63;
    float w = (n < 128) ? W1[n * NH + k] : W1[(n - 128) * NH + 64 + k];
    __half wh = __float2half_rn(w);
    __half wl = __float2half_rn(w - __half2float(wh));
    uint32_t off = (uint32_t)(n * 128 + ((k * 2) ^ ((n & 7) << 4)));
    *(__half*)(g_Wh + off) = wh;
    *(__half*)(g_Wl + off) = wl;
}

// ---------------------------------------------------------------------------
// m16n8k16 fp16 MMA, fp32 accumulators (sm_80+ PTX, portable to compute_103)
// ---------------------------------------------------------------------------
__device__ __forceinline__ void mma16816(float* c, const uint32_t* a,
                                         uint32_t b0, uint32_t b1) {
    asm volatile(
        "mma.sync.aligned.m16n8k16.row.col.f32.f16.f16.f32 "
        "{%0,%1,%2,%3}, {%4,%5,%6,%7}, {%8,%9}, {%0,%1,%2,%3};"
        : "+f"(c[0]), "+f"(c[1]), "+f"(c[2]), "+f"(c[3])
        : "r"(a[0]), "r"(a[1]), "r"(a[2]), "r"(a[3]), "r"(b0), "r"(b1));
}

// ---------------------------------------------------------------------------
// Kernel 1: node GEMM on tensor cores.
// D[128x256] = zh@Wh + zh@Wl  (W split exact; z fp16-rounded, err ~1.7e-4)
// ---------------------------------------------------------------------------
__global__ void __launch_bounds__(256) node_mma(const float* __restrict__ z,
                                                const float* __restrict__ b1) {
    extern __shared__ char smem[];
    const int tid  = threadIdx.x;
    const int wid  = tid >> 5;
    const int lane = tid & 31;
    const int gr   = lane >> 2;
    const int cc   = lane & 3;
    const int nodeBase = blockIdx.x * 128;

    if (tid < 128) ((float*)(smem + SM_B1))[tid] = b1[tid];

    {
        const uint4* sh = (const uint4*)g_Wh;
        const uint4* sl = (const uint4*)g_Wl;
        uint4* dh = (uint4*)(smem + SM_WH);
        uint4* dl = (uint4*)(smem + SM_WL);
        #pragma unroll
        for (int i = 0; i < 8; i++) {
            dh[tid + i * 256] = sh[tid + i * 256];
            dl[tid + i * 256] = sl[tid + i * 256];
        }
    }

    {
        #pragma unroll
        for (int i = 0; i < 16; i++) {
            int p    = tid + i * 256;
            int r    = p >> 5;
            int kp   = p & 31;
            int node = nodeBase + r;
            float2 zv = (node < N_NODES)
                      ? ((const float2*)z)[(size_t)node * 32 + kp]
                      : make_float2(0.f, 0.f);
            __half2 h = __floats2half2_rn(zv.x, zv.y);
            uint32_t off = (uint32_t)(r * 128 + ((4 * kp) ^ ((r & 7) << 4)));
            *(uint32_t*)(smem + SM_ZH + off) = *(const uint32_t*)&h;
        }
    }
    __syncthreads();

    const int rowlo = wid * 16 + gr;
    const int rowhi = rowlo + 8;
    const int sw    = gr << 4;
    uint32_t aH[4][4];
    #pragma unroll
    for (int ks = 0; ks < 4; ks++) {
        int k0 = ks * 32 + 4 * cc;
        int oLo = k0 ^ sw, oHi = (k0 + 16) ^ sw;
        aH[ks][0] = *(const uint32_t*)(smem + SM_ZH + rowlo * 128 + oLo);
        aH[ks][1] = *(const uint32_t*)(smem + SM_ZH + rowhi * 128 + oLo);
        aH[ks][2] = *(const uint32_t*)(smem + SM_ZH + rowlo * 128 + oHi);
        aH[ks][3] = *(const uint32_t*)(smem + SM_ZH + rowhi * 128 + oHi);
    }

    const int node0 = nodeBase + rowlo;
    const int node1 = nodeBase + rowhi;
    const float* sB1 = (const float*)(smem + SM_B1);

    #pragma unroll
    for (int pass = 0; pass < 2; pass++) {
        float acc[16][4];
        #pragma unroll
        for (int nt = 0; nt < 16; nt++)
            #pragma unroll
            for (int q = 0; q < 4; q++) acc[nt][q] = 0.f;

        #pragma unroll
        for (int ks = 0; ks < 4; ks++) {
            int k0  = ks * 32 + 4 * cc;
            int oLo = k0 ^ sw, oHi = (k0 + 16) ^ sw;
            #pragma unroll
            for (int nt = 0; nt < 16; nt++) {
                int n = (pass * 16 + nt) * 8 + gr;
                const char* bH = smem + SM_WH + n * 128;
                const char* bL = smem + SM_WL + n * 128;
                uint32_t h0 = *(const uint32_t*)(bH + oLo);
                uint32_t h1 = *(const uint32_t*)(bH + oHi);
                uint32_t l0 = *(const uint32_t*)(bL + oLo);
                uint32_t l1 = *(const uint32_t*)(bL + oHi);
                mma16816(acc[nt], aH[ks], h0, h1);
                mma16816(acc[nt], aH[ks], l0, l1);
            }
        }

        #pragma unroll
        for (int nt = 0; nt < 16; nt++) {
            int ntg = pass * 16 + nt;
            int col = ntg * 8 + 2 * cc;
            float add0 = 0.f, add1 = 0.f;
            __half* dstT;
            int c2;
            if (ntg < 16) { add0 = sB1[col]; add1 = sB1[col + 1]; dstT = g_Ah; c2 = col; }
            else          { dstT = g_Bh; c2 = col - 128; }
            __half2 d0 = __floats2half2_rn(acc[nt][0] + add0, acc[nt][1] + add1);
            __half2 d1 = __floats2half2_rn(acc[nt][2] + add0, acc[nt][3] + add1);
            if (node0 < N_NODES)
                *(uint32_t*)(dstT + (size_t)node0 * NH + c2) = *(const uint32_t*)&d0;
            if (node1 < N_NODES)
                *(uint32_t*)(dstT + (size_t)node1 * NH + c2) = *(const uint32_t*)&d1;
        }
    }
}

// ---------------------------------------------------------------------------
// Counting sort of edges by row (deterministic output values; scatter order
// within a bucket is irrelevant since each edge is computed independently).
// ---------------------------------------------------------------------------
__global__ void k_zero() {
    int i = blockIdx.x * 256 + threadIdx.x;
    if (i < N_NODES) g_cnt[i] = 0;
}
__global__ void k_hist(const int* __restrict__ row) {
    int e = blockIdx.x * 256 + threadIdx.x;
    if (e < N_EDGES) atomicAdd(&g_cnt[row[e]], 1u);
}
__global__ void k_scan1() {   // 98 blocks x 1024: per-block exclusive scan
    __shared__ unsigned int s[1024];
    int tid = threadIdx.x;
    int i = blockIdx.x * 1024 + tid;
    unsigned int v = (i < N_NODES) ? g_cnt[i] : 0u;
    s[tid] = v;
    __syncthreads();
    #pragma unroll
    for (int off = 1; off < 1024; off <<= 1) {
        unsigned int t = (tid >= off) ? s[tid - off] : 0u;
        __syncthreads();
        s[tid] += t;
        __syncthreads();
    }
    if (i < N_NODES) g_off[i] = s[tid] - v;
    if (tid == 1023) g_bsum[blockIdx.x] = s[1023];
}
__global__ void k_scan2(int nblk) {   // 1 thread: scan block sums
    if (threadIdx.x == 0 && blockIdx.x == 0) {
        unsigned int run = 0;
        for (int b = 0; b < nblk; b++) { g_bsc[b] = run; run += g_bsum[b]; }
    }
}
__global__ void k_scan3() {
    int i = blockIdx.x * 256 + threadIdx.x;
    if (i < N_NODES) {
        unsigned int o = g_off[i] + g_bsc[i >> 10];
        g_off[i] = o;
        g_cur[i] = o;
    }
}
__global__ void k_scatter(const int* __restrict__ row, const int* __restrict__ col) {
    int e = blockIdx.x * 256 + threadIdx.x;
    if (e < N_EDGES) {
        int r = row[e];
        unsigned int pos = atomicAdd(&g_cur[r], 1u);
        g_rowS[pos]  = r;
        g_colS[pos]  = col[e];
        g_permS[pos] = e;
    }
}

// ---------------------------------------------------------------------------
// Kernel 2: edge pass over ROW-SORTED edges. A-row loads become same-address
// L1 hits within each warp's 8-edge group (avg ~1.25 distinct rows/group),
// cutting A LTS traffic ~6x. out scattered via perm.
// ---------------------------------------------------------------------------
#define EDGE_BLOCKS 1184

__global__ void edge_kernel(const float* __restrict__ W2, const float* __restrict__ b2,
                            float* __restrict__ out) {
    const int lane = threadIdx.x & 31;
    const int warp = threadIdx.x >> 5;
    const int g    = lane >> 3;
    const int i    = lane & 7;

    const float4* W24 = (const float4*)W2;
    float4 w4[4];
    #pragma unroll
    for (int q = 0; q < 2; q++)
        #pragma unroll
        for (int h = 0; h < 2; h++)
            w4[q * 2 + h] = W24[(q * 8 + i) * 2 + h];
    const float bias = b2[0];

    const int warpGlobal = blockIdx.x * 8 + warp;
    const int nWarps     = EDGE_BLOCKS * 8;

    for (long e0 = (long)warpGlobal * 8; e0 < N_EDGES; e0 += (long)nWarps * 8) {
        const long eA = e0 + g;
        const long eB = e0 + 4 + g;

        const int rA = g_rowS[eA], cA = g_colS[eA], pA = g_permS[eA];
        const int rB = g_rowS[eB], cB = g_colS[eB], pB = g_permS[eB];

        const uint4* __restrict__ ArA = (const uint4*)(g_Ah + (size_t)rA * NH);
        const uint4* __restrict__ BcA = (const uint4*)(g_Bh + (size_t)cA * NH);
        const uint4* __restrict__ ArB = (const uint4*)(g_Ah + (size_t)rB * NH);
        const uint4* __restrict__ BcB = (const uint4*)(g_Bh + (size_t)cB * NH);

        uint4 avA[2], bvA[2], avB[2], bvB[2];
        #pragma unroll
        for (int q = 0; q < 2; q++) {
            avA[q] = ArA[q * 8 + i];  bvA[q] = BcA[q * 8 + i];
            avB[q] = ArB[q * 8 + i];  bvB[q] = BcB[q * 8 + i];
        }

        float sA = 0.f, sB = 0.f;
        #pragma unroll
        for (int q = 0; q < 2; q++) {
            const __half2* ahA = (const __half2*)&avA[q];
            const __half2* bhA = (const __half2*)&bvA[q];
            const __half2* ahB = (const __half2*)&avB[q];
            const __half2* bhB = (const __half2*)&bvB[q];
            const float* wq = (const float*)&w4[q * 2];
            #pragma unroll
            for (int t = 0; t < 4; t++) {
                float2 afA = __half22float2(ahA[t]);
                float2 bfA = __half22float2(bhA[t]);
                sA += wq[2 * t]     * fmaxf(afA.x + bfA.x, 0.f);
                sA += wq[2 * t + 1] * fmaxf(afA.y + bfA.y, 0.f);
                float2 afB = __half22float2(ahB[t]);
                float2 bfB = __half22float2(bhB[t]);
                sB += wq[2 * t]     * fmaxf(afB.x + bfB.x, 0.f);
                sB += wq[2 * t + 1] * fmaxf(afB.y + bfB.y, 0.f);
            }
        }

        sA += __shfl_xor_sync(0xffffffffu, sA, 1);
        sA += __shfl_xor_sync(0xffffffffu, sA, 2);
        sA += __shfl_xor_sync(0xffffffffu, sA, 4);
        sB += __shfl_xor_sync(0xffffffffu, sB, 1);
        sB += __shfl_xor_sync(0xffffffffu, sB, 2);
        sB += __shfl_xor_sync(0xffffffffu, sB, 4);

        if (i == 0) {
            out[pA] = sA + bias;
            out[pB] = sB + bias;
        }
    }
}

// ---------------------------------------------------------------------------
extern "C" void kernel_launch(void* const* d_in, const int* in_sizes, int n_in,
                              void* d_out, int out_size) {
    const float* z   = (const float*)d_in[0];
    const int*   row = (const int*)  d_in[1];
    const int*   col = (const int*)  d_in[2];
    const float* W1  = (const float*)d_in[3];
    const float* b1  = (const float*)d_in[4];
    const float* W2  = (const float*)d_in[5];
    const float* b2  = (const float*)d_in[6];
    float* out = (float*)d_out;

    cudaFuncSetAttribute(node_mma, cudaFuncAttributeMaxDynamicSharedMemorySize, SM_TOT);

    const int nodeBlk = (N_NODES + 255) / 256;      // 391
    const int edgeBlk = (N_EDGES + 255) / 256;      // 12500
    const int scanBlk = (N_NODES + 1023) / 1024;    // 98

    build_wt<<<64, 256>>>(W1);
    node_mma<<<(N_NODES + 127) / 128, 256, SM_TOT>>>(z, b1);

    k_zero<<<nodeBlk, 256>>>();
    k_hist<<<edgeBlk, 256>>>(row);
    k_scan1<<<scanBlk, 1024>>>();
    k_scan2<<<1, 32>>>(scanBlk);
    k_scan3<<<nodeBlk, 256>>>();
    k_scatter<<<edgeBlk, 256>>>(row, col);

    edge_kernel<<<EDGE_BLOCKS, 256>>>(W2, b2, out);
}

// round 8
// speedup vs baseline: 1.9231x; 1.9231x over previous
#include <cuda_runtime.h>
#include <cuda_fp16.h>
#include <cstdint>

#define N_NODES 100000
#define N_EDGES 3200000
#define D       64
#define NH      128

// ---------------------------------------------------------------------------
// Scratch (allocation-free rule: __device__ globals)
// ---------------------------------------------------------------------------
__device__ __half g_Ah[(size_t)N_NODES * NH];   // 25.6 MB: W1[:, :64] @ z + b1  (fp16)
__device__ __half g_Bh[(size_t)N_NODES * NH];   // 25.6 MB: W1[:, 64:] @ z       (fp16)
// Fused weight table [n=256][k=64] fp16, hi/lo split, XOR-swizzled:
//   byte(n,k) = n*128 + ((2k) ^ ((n&7)<<4))
__device__ unsigned char g_Wh[256 * 128];
__device__ unsigned char g_Wl[256 * 128];

// ---------------------------------------------------------------------------
// smem layout for node_mma (bytes)
// ---------------------------------------------------------------------------
#define SM_B1   0            // 512 B
#define SM_ZH   512          // 16 KB  zh [128 rows][128 B]
#define SM_WH   16896        // 32 KB  Wh [256 rows][128 B]
#define SM_WL   49664        // 32 KB  Wl
#define SM_TOT  82432

// ---------------------------------------------------------------------------
// Kernel 0: build split fp16 weight tables (swizzled).
//   n < 128 : W[n][k] = W1[n][k]          (A half)
//   n >=128 : W[n][k] = W1[n-128][64+k]   (B half)
// ---------------------------------------------------------------------------
__global__ void build_wt(const float* __restrict__ W1) {
    int idx = blockIdx.x * 256 + threadIdx.x;   // 0..16383
    int n = idx >> 6;
    int k = idx & 63;
    float w = (n < 128) ? W1[n * NH + k] : W1[(n - 128) * NH + 64 + k];
    __half wh = __float2half_rn(w);
    __half wl = __float2half_rn(w - __half2float(wh));
    uint32_t off = (uint32_t)(n * 128 + ((k * 2) ^ ((n & 7) << 4)));
    *(__half*)(g_Wh + off) = wh;
    *(__half*)(g_Wl + off) = wl;
}

// ---------------------------------------------------------------------------
// m16n8k16 fp16 MMA, fp32 accumulators (sm_80+ PTX, portable to compute_103)
// ---------------------------------------------------------------------------
__device__ __forceinline__ void mma16816(float* c, const uint32_t* a,
                                         uint32_t b0, uint32_t b1) {
    asm volatile(
        "mma.sync.aligned.m16n8k16.row.col.f32.f16.f16.f32 "
        "{%0,%1,%2,%3}, {%4,%5,%6,%7}, {%8,%9}, {%0,%1,%2,%3};"
        : "+f"(c[0]), "+f"(c[1]), "+f"(c[2]), "+f"(c[3])
        : "r"(a[0]), "r"(a[1]), "r"(a[2]), "r"(a[3]), "r"(b0), "r"(b1));
}

// ---------------------------------------------------------------------------
// Kernel 1: node GEMM on tensor cores.
// D[128x256] = zh@Wh + zh@Wl   (W split exact; z fp16-rounded, err ~1.7e-4)
// Warp w owns rows w*16..w*16+15; two passes of 16 n8-tiles (128 cols each).
// Epilogue: +b1 on A half, fp16 pack, store to g_Ah/g_Bh.
// ---------------------------------------------------------------------------
__global__ void __launch_bounds__(256) node_mma(const float* __restrict__ z,
                                                const float* __restrict__ b1) {
    extern __shared__ char smem[];
    const int tid  = threadIdx.x;
    const int wid  = tid >> 5;
    const int lane = tid & 31;
    const int gr   = lane >> 2;   // group row 0..7
    const int cc   = lane & 3;    // thread-in-group 0..3
    const int nodeBase = blockIdx.x * 128;

    if (tid < 128) ((float*)(smem + SM_B1))[tid] = b1[tid];

    // W tiles: linear copy (already swizzled in gmem)
    {
        const uint4* sh = (const uint4*)g_Wh;
        const uint4* sl = (const uint4*)g_Wl;
        uint4* dh = (uint4*)(smem + SM_WH);
        uint4* dl = (uint4*)(smem + SM_WL);
        #pragma unroll
        for (int i = 0; i < 8; i++) {
            dh[tid + i * 256] = sh[tid + i * 256];
            dl[tid + i * 256] = sl[tid + i * 256];
        }
    }

    // z tile: 128 rows x 64 cols fp32 -> zh fp16, swizzled
    {
        #pragma unroll
        for (int i = 0; i < 16; i++) {
            int p    = tid + i * 256;
            int r    = p >> 5;
            int kp   = p & 31;
            int node = nodeBase + r;
            float2 zv = (node < N_NODES)
                      ? ((const float2*)z)[(size_t)node * 32 + kp]
                      : make_float2(0.f, 0.f);
            __half2 h = __floats2half2_rn(zv.x, zv.y);
            uint32_t off = (uint32_t)(r * 128 + ((4 * kp) ^ ((r & 7) << 4)));
            *(uint32_t*)(smem + SM_ZH + off) = *(const uint32_t*)&h;
        }
    }
    __syncthreads();

    const int rowlo = wid * 16 + gr;
    const int rowhi = rowlo + 8;
    const int sw    = gr << 4;
    uint32_t aH[4][4];
    #pragma unroll
    for (int ks = 0; ks < 4; ks++) {
        int k0 = ks * 32 + 4 * cc;
        int oLo = k0 ^ sw, oHi = (k0 + 16) ^ sw;
        aH[ks][0] = *(const uint32_t*)(smem + SM_ZH + rowlo * 128 + oLo);
        aH[ks][1] = *(const uint32_t*)(smem + SM_ZH + rowhi * 128 + oLo);
        aH[ks][2] = *(const uint32_t*)(smem + SM_ZH + rowlo * 128 + oHi);
        aH[ks][3] = *(const uint32_t*)(smem + SM_ZH + rowhi * 128 + oHi);
    }

    const int node0 = nodeBase + rowlo;
    const int node1 = nodeBase + rowhi;
    const float* sB1 = (const float*)(smem + SM_B1);

    #pragma unroll
    for (int pass = 0; pass < 2; pass++) {
        float acc[16][4];
        #pragma unroll
        for (int nt = 0; nt < 16; nt++)
            #pragma unroll
            for (int q = 0; q < 4; q++) acc[nt][q] = 0.f;

        #pragma unroll
        for (int ks = 0; ks < 4; ks++) {
            int k0  = ks * 32 + 4 * cc;
            int oLo = k0 ^ sw, oHi = (k0 + 16) ^ sw;
            #pragma unroll
            for (int nt = 0; nt < 16; nt++) {
                int n = (pass * 16 + nt) * 8 + gr;
                const char* bH = smem + SM_WH + n * 128;
                const char* bL = smem + SM_WL + n * 128;
                uint32_t h0 = *(const uint32_t*)(bH + oLo);
                uint32_t h1 = *(const uint32_t*)(bH + oHi);
                uint32_t l0 = *(const uint32_t*)(bL + oLo);
                uint32_t l1 = *(const uint32_t*)(bL + oHi);
                mma16816(acc[nt], aH[ks], h0, h1);
                mma16816(acc[nt], aH[ks], l0, l1);
            }
        }

        #pragma unroll
        for (int nt = 0; nt < 16; nt++) {
            int ntg = pass * 16 + nt;
            int col = ntg * 8 + 2 * cc;
            float add0 = 0.f, add1 = 0.f;
            __half* dstT;
            int c2;
            if (ntg < 16) { add0 = sB1[col]; add1 = sB1[col + 1]; dstT = g_Ah; c2 = col; }
            else          { dstT = g_Bh; c2 = col - 128; }
            __half2 d0 = __floats2half2_rn(acc[nt][0] + add0, acc[nt][1] + add1);
            __half2 d1 = __floats2half2_rn(acc[nt][2] + add0, acc[nt][3] + add1);
            if (node0 < N_NODES)
                *(uint32_t*)(dstT + (size_t)node0 * NH + c2) = *(const uint32_t*)&d0;
            if (node1 < N_NODES)
                *(uint32_t*)(dstT + (size_t)node1 * NH + c2) = *(const uint32_t*)&d1;
        }
    }
}

// ---------------------------------------------------------------------------
// Kernel 2: edge pass (measured-best R4/R6 form): persistent grid-stride,
// direct row/col indexing. out[e] = W2 . relu(A[row]+B[col]) + b2.
// 8 lanes/edge, unroll-by-2 (8 edges/warp-iter). LTS-cap bound (~1.68 GB).
// ---------------------------------------------------------------------------
#define EDGE_BLOCKS 1184

__global__ void edge_kernel(const int* __restrict__ row, const int* __restrict__ col,
                            const float* __restrict__ W2, const float* __restrict__ b2,
                            float* __restrict__ out) {
    const int lane = threadIdx.x & 31;
    const int warp = threadIdx.x >> 5;
    const int g    = lane >> 3;
    const int i    = lane & 7;

    const float4* W24 = (const float4*)W2;
    float4 w4[4];
    #pragma unroll
    for (int q = 0; q < 2; q++)
        #pragma unroll
        for (int h = 0; h < 2; h++)
            w4[q * 2 + h] = W24[(q * 8 + i) * 2 + h];
    const float bias = b2[0];

    const int warpGlobal = blockIdx.x * 8 + warp;
    const int nWarps     = EDGE_BLOCKS * 8;

    for (long e0 = (long)warpGlobal * 8; e0 < N_EDGES; e0 += (long)nWarps * 8) {
        const long eA = e0 + g;
        const long eB = e0 + 4 + g;

        const int rA = row[eA], cA = col[eA];
        const int rB = row[eB], cB = col[eB];

        const uint4* __restrict__ ArA = (const uint4*)(g_Ah + (size_t)rA * NH);
        const uint4* __restrict__ BcA = (const uint4*)(g_Bh + (size_t)cA * NH);
        const uint4* __restrict__ ArB = (const uint4*)(g_Ah + (size_t)rB * NH);
        const uint4* __restrict__ BcB = (const uint4*)(g_Bh + (size_t)cB * NH);

        uint4 avA[2], bvA[2], avB[2], bvB[2];
        #pragma unroll
        for (int q = 0; q < 2; q++) {
            avA[q] = ArA[q * 8 + i];  bvA[q] = BcA[q * 8 + i];
            avB[q] = ArB[q * 8 + i];  bvB[q] = BcB[q * 8 + i];
        }

        float sA = 0.f, sB = 0.f;
        #pragma unroll
        for (int q = 0; q < 2; q++) {
            const __half2* ahA = (const __half2*)&avA[q];
            const __half2* bhA = (const __half2*)&bvA[q];
            const __half2* ahB = (const __half2*)&avB[q];
            const __half2* bhB = (const __half2*)&bvB[q];
            const float* wq = (const float*)&w4[q * 2];
            #pragma unroll
            for (int t = 0; t < 4; t++) {
                float2 afA = __half22float2(ahA[t]);
                float2 bfA = __half22float2(bhA[t]);
                sA += wq[2 * t]     * fmaxf(afA.x + bfA.x, 0.f);
                sA += wq[2 * t + 1] * fmaxf(afA.y + bfA.y, 0.f);
                float2 afB = __half22float2(ahB[t]);
                float2 bfB = __half22float2(bhB[t]);
                sB += wq[2 * t]     * fmaxf(afB.x + bfB.x, 0.f);
                sB += wq[2 * t + 1] * fmaxf(afB.y + bfB.y, 0.f);
            }
        }

        sA += __shfl_xor_sync(0xffffffffu, sA, 1);
        sA += __shfl_xor_sync(0xffffffffu, sA, 2);
        sA += __shfl_xor_sync(0xffffffffu, sA, 4);
        sB += __shfl_xor_sync(0xffffffffu, sB, 1);
        sB += __shfl_xor_sync(0xffffffffu, sB, 2);
        sB += __shfl_xor_sync(0xffffffffu, sB, 4);

        if (i == 0) {
            out[eA] = sA + bias;
            out[eB] = sB + bias;
        }
    }
}

// ---------------------------------------------------------------------------
extern "C" void kernel_launch(void* const* d_in, const int* in_sizes, int n_in,
                              void* d_out, int out_size) {
    const float* z   = (const float*)d_in[0];
    const int*   row = (const int*)  d_in[1];
    const int*   col = (const int*)  d_in[2];
    const float* W1  = (const float*)d_in[3];
    const float* b1  = (const float*)d_in[4];
    const float* W2  = (const float*)d_in[5];
    const float* b2  = (const float*)d_in[6];
    float* out = (float*)d_out;

    cudaFuncSetAttribute(node_mma, cudaFuncAttributeMaxDynamicSharedMemorySize, SM_TOT);

    build_wt<<<64, 256>>>(W1);
    node_mma<<<(N_NODES + 127) / 128, 256, SM_TOT>>>(z, b1);      // 782 blocks
    edge_kernel<<<EDGE_BLOCKS, 256>>>(row, col, W2, b2, out);     // persistent
}

// round 9
// speedup vs baseline: 1.9504x; 1.0142x over previous
#include <cuda_runtime.h>
#include <cuda_fp16.h>
#include <cstdint>

#define N_NODES 100000
#define N_EDGES 3200000
#define D       64
#define NH      128

// ---------------------------------------------------------------------------
// Scratch (allocation-free rule: __device__ globals)
// ---------------------------------------------------------------------------
__device__ __half g_Ah[(size_t)N_NODES * NH];   // 25.6 MB: W1[:, :64] @ z + b1  (fp16)
__device__ __half g_Bh[(size_t)N_NODES * NH];   // 25.6 MB: W1[:, 64:] @ z       (fp16)

// ---------------------------------------------------------------------------
// smem layout for node_mma (bytes)
// ---------------------------------------------------------------------------
#define SM_B1   0            // 512 B
#define SM_ZH   512          // 16 KB  zh [128 rows][128 B]
#define SM_WH   16896        // 32 KB  Wh [256 rows][128 B]  (fused, swizzled)
#define SM_TOT  49664

// ---------------------------------------------------------------------------
// m16n8k16 fp16 MMA, fp32 accumulators (sm_80+ PTX, portable to compute_103)
// ---------------------------------------------------------------------------
__device__ __forceinline__ void mma16816(float* c, const uint32_t* a,
                                         uint32_t b0, uint32_t b1) {
    asm volatile(
        "mma.sync.aligned.m16n8k16.row.col.f32.f16.f16.f32 "
        "{%0,%1,%2,%3}, {%4,%5,%6,%7}, {%8,%9}, {%0,%1,%2,%3};"
        : "+f"(c[0]), "+f"(c[1]), "+f"(c[2]), "+f"(c[3])
        : "r"(a[0]), "r"(a[1]), "r"(a[2]), "r"(a[3]), "r"(b0), "r"(b1));
}

// ---------------------------------------------------------------------------
// Kernel 1: node GEMM on tensor cores (fused W conversion, single fp16 MMA).
// D[128 nodes x 256 cols] = zh[128x64] @ Wh[64x256]  (fp32 accum)
// Fused weight layout in smem: row n (0..255) = output col; n<128 -> A half
// (W1[n][k]), n>=128 -> B half (W1[n-128][64+k]); byte(n,k) swizzled:
//   n*128 + ((2k) ^ ((n&7)<<4))
// Warp w owns node rows w*16..w*16+15; 2 passes x 16 n8-tiles.
// Epilogue: +b1 on A half, fp16 pack, store to g_Ah/g_Bh.
// ---------------------------------------------------------------------------
__global__ void __launch_bounds__(256) node_mma(const float* __restrict__ z,
                                                const float* __restrict__ W1,
                                                const float* __restrict__ b1) {
    extern __shared__ char smem[];
    const int tid  = threadIdx.x;
    const int wid  = tid >> 5;
    const int lane = tid & 31;
    const int gr   = lane >> 2;   // group row 0..7
    const int cc   = lane & 3;    // thread-in-group 0..3
    const int nodeBase = blockIdx.x * 128;

    if (tid < 128) ((float*)(smem + SM_B1))[tid] = b1[tid];

    // Fused W conversion: W1 fp32 -> swizzled fp16 smem (coalesced L2 reads)
    #pragma unroll
    for (int it = 0; it < 64; it++) {
        int idx = tid + it * 256;       // 0..16383
        int n = idx >> 6;
        int k = idx & 63;
        float w = (n < 128) ? W1[n * NH + k] : W1[(n - 128) * NH + 64 + k];
        uint32_t off = (uint32_t)(n * 128 + ((k * 2) ^ ((n & 7) << 4)));
        *(__half*)(smem + SM_WH + off) = __float2half_rn(w);
    }

    // z tile: 128 rows x 64 cols fp32 -> zh fp16, swizzled
    #pragma unroll
    for (int i = 0; i < 16; i++) {
        int p    = tid + i * 256;
        int r    = p >> 5;
        int kp   = p & 31;
        int node = nodeBase + r;
        float2 zv = (node < N_NODES)
                  ? ((const float2*)z)[(size_t)node * 32 + kp]
                  : make_float2(0.f, 0.f);
        __half2 h = __floats2half2_rn(zv.x, zv.y);
        uint32_t off = (uint32_t)(r * 128 + ((4 * kp) ^ ((r & 7) << 4)));
        *(uint32_t*)(smem + SM_ZH + off) = *(const uint32_t*)&h;
    }
    __syncthreads();

    const int rowlo = wid * 16 + gr;
    const int rowhi = rowlo + 8;
    const int sw    = gr << 4;
    uint32_t aH[4][4];
    #pragma unroll
    for (int ks = 0; ks < 4; ks++) {
        int k0 = ks * 32 + 4 * cc;
        int oLo = k0 ^ sw, oHi = (k0 + 16) ^ sw;
        aH[ks][0] = *(const uint32_t*)(smem + SM_ZH + rowlo * 128 + oLo);
        aH[ks][1] = *(const uint32_t*)(smem + SM_ZH + rowhi * 128 + oLo);
        aH[ks][2] = *(const uint32_t*)(smem + SM_ZH + rowlo * 128 + oHi);
        aH[ks][3] = *(const uint32_t*)(smem + SM_ZH + rowhi * 128 + oHi);
    }

    const int node0 = nodeBase + rowlo;
    const int node1 = nodeBase + rowhi;
    const float* sB1 = (const float*)(smem + SM_B1);

    #pragma unroll
    for (int pass = 0; pass < 2; pass++) {
        float acc[16][4];
        #pragma unroll
        for (int nt = 0; nt < 16; nt++)
            #pragma unroll
            for (int q = 0; q < 4; q++) acc[nt][q] = 0.f;

        #pragma unroll
        for (int ks = 0; ks < 4; ks++) {
            int k0  = ks * 32 + 4 * cc;
            int oLo = k0 ^ sw, oHi = (k0 + 16) ^ sw;
            #pragma unroll
            for (int nt = 0; nt < 16; nt++) {
                int n = (pass * 16 + nt) * 8 + gr;
                const char* bH = smem + SM_WH + n * 128;
                uint32_t h0 = *(const uint32_t*)(bH + oLo);
                uint32_t h1 = *(const uint32_t*)(bH + oHi);
                mma16816(acc[nt], aH[ks], h0, h1);
            }
        }

        #pragma unroll
        for (int nt = 0; nt < 16; nt++) {
            int ntg = pass * 16 + nt;
            int col = ntg * 8 + 2 * cc;
            float add0 = 0.f, add1 = 0.f;
            __half* dstT;
            int c2;
            if (ntg < 16) { add0 = sB1[col]; add1 = sB1[col + 1]; dstT = g_Ah; c2 = col; }
            else          { dstT = g_Bh; c2 = col - 128; }
            __half2 d0 = __floats2half2_rn(acc[nt][0] + add0, acc[nt][1] + add1);
            __half2 d1 = __floats2half2_rn(acc[nt][2] + add0, acc[nt][3] + add1);
            if (node0 < N_NODES)
                *(uint32_t*)(dstT + (size_t)node0 * NH + c2) = *(const uint32_t*)&d0;
            if (node1 < N_NODES)
                *(uint32_t*)(dstT + (size_t)node1 * NH + c2) = *(const uint32_t*)&d1;
        }
    }
}

// ---------------------------------------------------------------------------
// Kernel 2: edge pass (measured-best form): persistent grid-stride, direct
// row/col indexing. out[e] = W2 . relu(A[row]+B[col]) + b2.
// 8 lanes/edge, unroll-by-2 (8 edges/warp-iter). LTS-cap bound (~1.68 GB).
// ---------------------------------------------------------------------------
#define EDGE_BLOCKS 1184

__global__ void edge_kernel(const int* __restrict__ row, const int* __restrict__ col,
                            const float* __restrict__ W2, const float* __restrict__ b2,
                            float* __restrict__ out) {
    const int lane = threadIdx.x & 31;
    const int warp = threadIdx.x >> 5;
    const int g    = lane >> 3;
    const int i    = lane & 7;

    const float4* W24 = (const float4*)W2;
    float4 w4[4];
    #pragma unroll
    for (int q = 0; q < 2; q++)
        #pragma unroll
        for (int h = 0; h < 2; h++)
            w4[q * 2 + h] = W24[(q * 8 + i) * 2 + h];
    const float bias = b2[0];

    const int warpGlobal = blockIdx.x * 8 + warp;
    const int nWarps     = EDGE_BLOCKS * 8;

    for (long e0 = (long)warpGlobal * 8; e0 < N_EDGES; e0 += (long)nWarps * 8) {
        const long eA = e0 + g;
        const long eB = e0 + 4 + g;

        const int rA = row[eA], cA = col[eA];
        const int rB = row[eB], cB = col[eB];

        const uint4* __restrict__ ArA = (const uint4*)(g_Ah + (size_t)rA * NH);
        const uint4* __restrict__ BcA = (const uint4*)(g_Bh + (size_t)cA * NH);
        const uint4* __restrict__ ArB = (const uint4*)(g_Ah + (size_t)rB * NH);
        const uint4* __restrict__ BcB = (const uint4*)(g_Bh + (size_t)cB * NH);

        uint4 avA[2], bvA[2], avB[2], bvB[2];
        #pragma unroll
        for (int q = 0; q < 2; q++) {
            avA[q] = ArA[q * 8 + i];  bvA[q] = BcA[q * 8 + i];
            avB[q] = ArB[q * 8 + i];  bvB[q] = BcB[q * 8 + i];
        }

        float sA = 0.f, sB = 0.f;
        #pragma unroll
        for (int q = 0; q < 2; q++) {
            const __half2* ahA = (const __half2*)&avA[q];
            const __half2* bhA = (const __half2*)&bvA[q];
            const __half2* ahB = (const __half2*)&avB[q];
            const __half2* bhB = (const __half2*)&bvB[q];
            const float* wq = (const float*)&w4[q * 2];
            #pragma unroll
            for (int t = 0; t < 4; t++) {
                float2 afA = __half22float2(ahA[t]);
                float2 bfA = __half22float2(bhA[t]);
                sA += wq[2 * t]     * fmaxf(afA.x + bfA.x, 0.f);
                sA += wq[2 * t + 1] * fmaxf(afA.y + bfA.y, 0.f);
                float2 afB = __half22float2(ahB[t]);
                float2 bfB = __half22float2(bhB[t]);
                sB += wq[2 * t]     * fmaxf(afB.x + bfB.x, 0.f);
                sB += wq[2 * t + 1] * fmaxf(afB.y + bfB.y, 0.f);
            }
        }

        sA += __shfl_xor_sync(0xffffffffu, sA, 1);
        sA += __shfl_xor_sync(0xffffffffu, sA, 2);
        sA += __shfl_xor_sync(0xffffffffu, sA, 4);
        sB += __shfl_xor_sync(0xffffffffu, sB, 1);
        sB += __shfl_xor_sync(0xffffffffu, sB, 2);
        sB += __shfl_xor_sync(0xffffffffu, sB, 4);

        if (i == 0) {
            out[eA] = sA + bias;
            out[eB] = sB + bias;
        }
    }
}

// ---------------------------------------------------------------------------
extern "C" void kernel_launch(void* const* d_in, const int* in_sizes, int n_in,
                              void* d_out, int out_size) {
    const float* z   = (const float*)d_in[0];
    const int*   row = (const int*)  d_in[1];
    const int*   col = (const int*)  d_in[2];
    const float* W1  = (const float*)d_in[3];
    const float* b1  = (const float*)d_in[4];
    const float* W2  = (const float*)d_in[5];
    const float* b2  = (const float*)d_in[6];
    float* out = (float*)d_out;

    cudaFuncSetAttribute(node_mma, cudaFuncAttributeMaxDynamicSharedMemorySize, SM_TOT);

    node_mma<<<(N_NODES + 127) / 128, 256, SM_TOT>>>(z, W1, b1);  // 782 blocks
    edge_kernel<<<EDGE_BLOCKS, 256>>>(row, col, W2, b2, out);     // persistent
}

// round 10
// speedup vs baseline: 2.2268x; 1.1417x over previous
#include <cuda_runtime.h>
#include <cuda_fp16.h>
#include <cstdint>

#define N_NODES 100000
#define N_EDGES 3200000
#define D       64
#define NH      128

// ---------------------------------------------------------------------------
// Scratch (allocation-free rule: __device__ globals)
// ---------------------------------------------------------------------------
__device__ __half g_Ah[(size_t)N_NODES * NH];   // 25.6 MB: W1[:, :64] @ z + b1  (fp16)
__device__ __half g_Bh[(size_t)N_NODES * NH];   // 25.6 MB: W1[:, 64:] @ z       (fp16)

// ---------------------------------------------------------------------------
// smem layout for node_mma (bytes)
// ---------------------------------------------------------------------------
#define SM_B1   0            // 512 B
#define SM_ZH   512          // 16 KB  zh [128 rows][128 B]
#define SM_WH   16896        // 32 KB  Wh [256 rows][128 B]  (fused, swizzled)
#define SM_TOT  49664

// ---------------------------------------------------------------------------
// m16n8k16 fp16 MMA, fp32 accumulators (sm_80+ PTX, portable to compute_103)
// ---------------------------------------------------------------------------
__device__ __forceinline__ void mma16816(float* c, const uint32_t* a,
                                         uint32_t b0, uint32_t b1) {
    asm volatile(
        "mma.sync.aligned.m16n8k16.row.col.f32.f16.f16.f32 "
        "{%0,%1,%2,%3}, {%4,%5,%6,%7}, {%8,%9}, {%0,%1,%2,%3};"
        : "+f"(c[0]), "+f"(c[1]), "+f"(c[2]), "+f"(c[3])
        : "r"(a[0]), "r"(a[1]), "r"(a[2]), "r"(a[3]), "r"(b0), "r"(b1));
}

// ---------------------------------------------------------------------------
// Kernel 1: node GEMM on tensor cores (fused W conversion, single fp16 MMA).
// D[128 nodes x 256 cols] = zh[128x64] @ Wh[64x256]  (fp32 accum)
// ---------------------------------------------------------------------------
__global__ void __launch_bounds__(256) node_mma(const float* __restrict__ z,
                                                const float* __restrict__ W1,
                                                const float* __restrict__ b1) {
    extern __shared__ char smem[];
    const int tid  = threadIdx.x;
    const int wid  = tid >> 5;
    const int lane = tid & 31;
    const int gr   = lane >> 2;   // group row 0..7
    const int cc   = lane & 3;    // thread-in-group 0..3
    const int nodeBase = blockIdx.x * 128;

    if (tid < 128) ((float*)(smem + SM_B1))[tid] = b1[tid];

    // Fused W conversion: W1 fp32 -> swizzled fp16 smem (coalesced L2 reads)
    #pragma unroll
    for (int it = 0; it < 64; it++) {
        int idx = tid + it * 256;       // 0..16383
        int n = idx >> 6;
        int k = idx & 63;
        float w = (n < 128) ? W1[n * NH + k] : W1[(n - 128) * NH + 64 + k];
        uint32_t off = (uint32_t)(n * 128 + ((k * 2) ^ ((n & 7) << 4)));
        *(__half*)(smem + SM_WH + off) = __float2half_rn(w);
    }

    // z tile: 128 rows x 64 cols fp32 -> zh fp16, swizzled
    #pragma unroll
    for (int i = 0; i < 16; i++) {
        int p    = tid + i * 256;
        int r    = p >> 5;
        int kp   = p & 31;
        int node = nodeBase + r;
        float2 zv = (node < N_NODES)
                  ? ((const float2*)z)[(size_t)node * 32 + kp]
                  : make_float2(0.f, 0.f);
        __half2 h = __floats2half2_rn(zv.x, zv.y);
        uint32_t off = (uint32_t)(r * 128 + ((4 * kp) ^ ((r & 7) << 4)));
        *(uint32_t*)(smem + SM_ZH + off) = *(const uint32_t*)&h;
    }
    __syncthreads();

    const int rowlo = wid * 16 + gr;
    const int rowhi = rowlo + 8;
    const int sw    = gr << 4;
    uint32_t aH[4][4];
    #pragma unroll
    for (int ks = 0; ks < 4; ks++) {
        int k0 = ks * 32 + 4 * cc;
        int oLo = k0 ^ sw, oHi = (k0 + 16) ^ sw;
        aH[ks][0] = *(const uint32_t*)(smem + SM_ZH + rowlo * 128 + oLo);
        aH[ks][1] = *(const uint32_t*)(smem + SM_ZH + rowhi * 128 + oLo);
        aH[ks][2] = *(const uint32_t*)(smem + SM_ZH + rowlo * 128 + oHi);
        aH[ks][3] = *(const uint32_t*)(smem + SM_ZH + rowhi * 128 + oHi);
    }

    const int node0 = nodeBase + rowlo;
    const int node1 = nodeBase + rowhi;
    const float* sB1 = (const float*)(smem + SM_B1);

    #pragma unroll
    for (int pass = 0; pass < 2; pass++) {
        float acc[16][4];
        #pragma unroll
        for (int nt = 0; nt < 16; nt++)
            #pragma unroll
            for (int q = 0; q < 4; q++) acc[nt][q] = 0.f;

        #pragma unroll
        for (int ks = 0; ks < 4; ks++) {
            int k0  = ks * 32 + 4 * cc;
            int oLo = k0 ^ sw, oHi = (k0 + 16) ^ sw;
            #pragma unroll
            for (int nt = 0; nt < 16; nt++) {
                int n = (pass * 16 + nt) * 8 + gr;
                const char* bH = smem + SM_WH + n * 128;
                uint32_t h0 = *(const uint32_t*)(bH + oLo);
                uint32_t h1 = *(const uint32_t*)(bH + oHi);
                mma16816(acc[nt], aH[ks], h0, h1);
            }
        }

        #pragma unroll
        for (int nt = 0; nt < 16; nt++) {
            int ntg = pass * 16 + nt;
            int col = ntg * 8 + 2 * cc;
            float add0 = 0.f, add1 = 0.f;
            __half* dstT;
            int c2;
            if (ntg < 16) { add0 = sB1[col]; add1 = sB1[col + 1]; dstT = g_Ah; c2 = col; }
            else          { dstT = g_Bh; c2 = col - 128; }
            __half2 d0 = __floats2half2_rn(acc[nt][0] + add0, acc[nt][1] + add1);
            __half2 d1 = __floats2half2_rn(acc[nt][2] + add0, acc[nt][3] + add1);
            if (node0 < N_NODES)
                *(uint32_t*)(dstT + (size_t)node0 * NH + c2) = *(const uint32_t*)&d0;
            if (node1 < N_NODES)
                *(uint32_t*)(dstT + (size_t)node1 * NH + c2) = *(const uint32_t*)&d1;
        }
    }
}

// ---------------------------------------------------------------------------
// Kernel 2: edge pass. out[e] = W2 . relu(A[row]+B[col]) + b2
// add + relu done in HALF2 (2 elem/instr), dot accumulated in fp32.
// Math per lane-edge: 8 HADD2 + 8 HMAX2 + 16 F2F + 16 FFMA (was ~80 instrs).
// Persistent grid-stride, 8 lanes/edge, unroll-by-2 (8 edges/warp-iter).
// ---------------------------------------------------------------------------
#define EDGE_BLOCKS 1184

__global__ void edge_kernel(const int* __restrict__ row, const int* __restrict__ col,
                            const float* __restrict__ W2, const float* __restrict__ b2,
                            float* __restrict__ out) {
    const int lane = threadIdx.x & 31;
    const int warp = threadIdx.x >> 5;
    const int g    = lane >> 3;
    const int i    = lane & 7;

    const float4* W24 = (const float4*)W2;
    float4 w4[4];
    #pragma unroll
    for (int q = 0; q < 2; q++)
        #pragma unroll
        for (int h = 0; h < 2; h++)
            w4[q * 2 + h] = W24[(q * 8 + i) * 2 + h];
    const float bias = b2[0];
    const __half2 zero2 = __float2half2_rn(0.f);

    const int warpGlobal = blockIdx.x * 8 + warp;
    const int nWarps     = EDGE_BLOCKS * 8;

    for (long e0 = (long)warpGlobal * 8; e0 < N_EDGES; e0 += (long)nWarps * 8) {
        const long eA = e0 + g;
        const long eB = e0 + 4 + g;

        const int rA = row[eA], cA = col[eA];
        const int rB = row[eB], cB = col[eB];

        const uint4* __restrict__ ArA = (const uint4*)(g_Ah + (size_t)rA * NH);
        const uint4* __restrict__ BcA = (const uint4*)(g_Bh + (size_t)cA * NH);
        const uint4* __restrict__ ArB = (const uint4*)(g_Ah + (size_t)rB * NH);
        const uint4* __restrict__ BcB = (const uint4*)(g_Bh + (size_t)cB * NH);

        uint4 avA[2], bvA[2], avB[2], bvB[2];
        #pragma unroll
        for (int q = 0; q < 2; q++) {
            avA[q] = ArA[q * 8 + i];  bvA[q] = BcA[q * 8 + i];
            avB[q] = ArB[q * 8 + i];  bvB[q] = BcB[q * 8 + i];
        }

        float sA = 0.f, sB = 0.f;
        #pragma unroll
        for (int q = 0; q < 2; q++) {
            const __half2* ahA = (const __half2*)&avA[q];
            const __half2* bhA = (const __half2*)&bvA[q];
            const __half2* ahB = (const __half2*)&avB[q];
            const __half2* bhB = (const __half2*)&bvB[q];
            const float* wq = (const float*)&w4[q * 2];
            #pragma unroll
            for (int t = 0; t < 4; t++) {
                __half2 hA = __hmax2(__hadd2(ahA[t], bhA[t]), zero2);
                __half2 hB = __hmax2(__hadd2(ahB[t], bhB[t]), zero2);
                float2 fA = __half22float2(hA);
                float2 fB = __half22float2(hB);
                sA += wq[2 * t]     * fA.x;
                sA += wq[2 * t + 1] * fA.y;
                sB += wq[2 * t]     * fB.x;
                sB += wq[2 * t + 1] * fB.y;
            }
        }

        sA += __shfl_xor_sync(0xffffffffu, sA, 1);
        sA += __shfl_xor_sync(0xffffffffu, sA, 2);
        sA += __shfl_xor_sync(0xffffffffu, sA, 4);
        sB += __shfl_xor_sync(0xffffffffu, sB, 1);
        sB += __shfl_xor_sync(0xffffffffu, sB, 2);
        sB += __shfl_xor_sync(0xffffffffu, sB, 4);

        if (i == 0) {
            out[eA] = sA + bias;
            out[eB] = sB + bias;
        }
    }
}

// ---------------------------------------------------------------------------
extern "C" void kernel_launch(void* const* d_in, const int* in_sizes, int n_in,
                              void* d_out, int out_size) {
    const float* z   = (const float*)d_in[0];
    const int*   row = (const int*)  d_in[1];
    const int*   col = (const int*)  d_in[2];
    const float* W1  = (const float*)d_in[3];
    const float* b1  = (const float*)d_in[4];
    const float* W2  = (const float*)d_in[5];
    const float* b2  = (const float*)d_in[6];
    float* out = (float*)d_out;

    cudaFuncSetAttribute(node_mma, cudaFuncAttributeMaxDynamicSharedMemorySize, SM_TOT);

    node_mma<<<(N_NODES + 127) / 128, 256, SM_TOT>>>(z, W1, b1);  // 782 blocks
    edge_kernel<<<EDGE_BLOCKS, 256>>>(row, col, W2, b2, out);     // persistent
}